// round 3
// baseline (speedup 1.0000x reference)
#include <cuda_runtime.h>
#include <math.h>

#define TT 512
#define BB 64
#define II 1024
#define HH 1024
#define NG 4096   // 4*H

// Scratch (allocation-free rule: __device__ globals)
__device__ __align__(16) float g_xg[(size_t)TT * BB * NG];  // x@W_ih^T + b_ih, [T,B,4H]
__device__ __align__(16) float g_c[BB * HH];                // cell state

// ---------------------------------------------------------------------------
// Input GEMM: g_xg[m, n] = sum_k x[m,k] * W_ih[n,k] + b_ih[n]
// M = T*B = 32768, N = 4096, K = 1024. 128x128 tile, KC=16, 256 thr, 8x8 micro.
// ---------------------------------------------------------------------------
__global__ __launch_bounds__(256, 2) void xgemm_kernel(
    const float* __restrict__ A,     // x  [M, K]
    const float* __restrict__ W,     // W_ih [N, K]
    const float* __restrict__ bias)  // b_ih [N]
{
    __shared__ float sA[16][132];
    __shared__ float sB[16][132];

    const int K = II;
    const int bn = blockIdx.x * 128;
    const int bm = blockIdx.y * 128;
    const int tid = threadIdx.x;
    const int tx = tid & 15;       // 0..15 -> cols tx*8
    const int ty = tid >> 4;       // 0..15 -> rows ty*8

    const int lrow = tid >> 1;         // 0..127
    const int lkq  = (tid & 1) * 8;    // 0 or 8

    const float* Aptr = A + (size_t)(bm + lrow) * K + lkq;
    const float* Wptr = W + (size_t)(bn + lrow) * K + lkq;

    float acc[8][8];
#pragma unroll
    for (int i = 0; i < 8; i++)
#pragma unroll
        for (int j = 0; j < 8; j++) acc[i][j] = 0.f;

    // prefetch chunk 0 into registers
    float4 ra0 = *(const float4*)(Aptr);
    float4 ra1 = *(const float4*)(Aptr + 4);
    float4 rb0 = *(const float4*)(Wptr);
    float4 rb1 = *(const float4*)(Wptr + 4);

    // NOTE: outer loop must NOT be unrolled (code-size / compile-time bound).
#pragma unroll 1
    for (int c = 0; c < K / 16; c++) {
        __syncthreads();   // previous compute done reading smem
        sA[lkq + 0][lrow] = ra0.x; sA[lkq + 1][lrow] = ra0.y;
        sA[lkq + 2][lrow] = ra0.z; sA[lkq + 3][lrow] = ra0.w;
        sA[lkq + 4][lrow] = ra1.x; sA[lkq + 5][lrow] = ra1.y;
        sA[lkq + 6][lrow] = ra1.z; sA[lkq + 7][lrow] = ra1.w;
        sB[lkq + 0][lrow] = rb0.x; sB[lkq + 1][lrow] = rb0.y;
        sB[lkq + 2][lrow] = rb0.z; sB[lkq + 3][lrow] = rb0.w;
        sB[lkq + 4][lrow] = rb1.x; sB[lkq + 5][lrow] = rb1.y;
        sB[lkq + 6][lrow] = rb1.z; sB[lkq + 7][lrow] = rb1.w;
        __syncthreads();

        if (c + 1 < K / 16) {       // prefetch next chunk (hidden under compute)
            int ko = (c + 1) * 16;
            ra0 = *(const float4*)(Aptr + ko);
            ra1 = *(const float4*)(Aptr + ko + 4);
            rb0 = *(const float4*)(Wptr + ko);
            rb1 = *(const float4*)(Wptr + ko + 4);
        }

#pragma unroll
        for (int kk = 0; kk < 16; kk++) {
            float4 x0 = *(const float4*)&sA[kk][ty * 8];
            float4 x1 = *(const float4*)&sA[kk][ty * 8 + 4];
            float4 y0 = *(const float4*)&sB[kk][tx * 8];
            float4 y1 = *(const float4*)&sB[kk][tx * 8 + 4];
            float av[8] = {x0.x, x0.y, x0.z, x0.w, x1.x, x1.y, x1.z, x1.w};
            float bv[8] = {y0.x, y0.y, y0.z, y0.w, y1.x, y1.y, y1.z, y1.w};
#pragma unroll
            for (int i = 0; i < 8; i++)
#pragma unroll
                for (int j = 0; j < 8; j++) acc[i][j] += av[i] * bv[j];
        }
    }

    float bv[8];
#pragma unroll
    for (int j = 0; j < 8; j++) bv[j] = bias[bn + tx * 8 + j];

#pragma unroll
    for (int i = 0; i < 8; i++) {
        size_t row = (size_t)(bm + ty * 8 + i);
        float* cp = g_xg + row * NG + bn + tx * 8;
        float4 v0 = make_float4(acc[i][0] + bv[0], acc[i][1] + bv[1],
                                acc[i][2] + bv[2], acc[i][3] + bv[3]);
        float4 v1 = make_float4(acc[i][4] + bv[4], acc[i][5] + bv[5],
                                acc[i][6] + bv[6], acc[i][7] + bv[7]);
        *(float4*)cp = v0;
        *(float4*)(cp + 4) = v1;
    }
}

// ---------------------------------------------------------------------------
// Fused LSTM step. Block j handles h-columns [j*8, j*8+8) of ALL FOUR gates:
// a 64x32 GEMM tile (K=1024) against 32 scattered W_hh rows, then the
// pointwise gate update for its 64x8 h/c slice. grid=128, block=128.
// ---------------------------------------------------------------------------
__device__ __forceinline__ float sigf(float x) { return 1.f / (1.f + expf(-x)); }

__global__ __launch_bounds__(128, 1) void lstm_step_kernel(
    const float* __restrict__ Hprev,  // [64, 1024]
    const float* __restrict__ Whh,    // [4096, 1024]
    const float* __restrict__ bhh,    // [4096]
    float* __restrict__ Hout,         // [64, 1024]
    int t)
{
    __shared__ float sH[2][16][68];
    __shared__ float sW[2][16][36];
    __shared__ float sG[64][33];

    const int tid = threadIdx.x;
    const int j0 = blockIdx.x * 8;
    const int tx = tid & 15;     // cols tx*2, tx*2+1 (local 0..31)
    const int ty = tid >> 4;     // rows ty*8 .. ty*8+7

    // load-index mapping
    const int hrow = tid >> 1;           // 0..63
    const int hkq  = (tid & 1) * 8;      // 0 or 8
    const int wn   = tid >> 2;           // 0..31 local gate-col
    const int wkq  = (tid & 3) * 4;      // 0,4,8,12
    const int wglob = (wn >> 3) * HH + j0 + (wn & 7);   // W_hh row

    const float* Hptr = Hprev + (size_t)hrow * II + hkq;
    const float* Wptr = Whh + (size_t)wglob * II + wkq;
    const float* xg_t = g_xg + (size_t)t * BB * NG;

    float acc[8][2];
#pragma unroll
    for (int r = 0; r < 8; r++) { acc[r][0] = 0.f; acc[r][1] = 0.f; }

    // prologue: chunk 0 -> buffer 0
    {
        float4 ha = *(const float4*)(Hptr);
        float4 hb = *(const float4*)(Hptr + 4);
        float4 wv = *(const float4*)(Wptr);
        sH[0][hkq + 0][hrow] = ha.x; sH[0][hkq + 1][hrow] = ha.y;
        sH[0][hkq + 2][hrow] = ha.z; sH[0][hkq + 3][hrow] = ha.w;
        sH[0][hkq + 4][hrow] = hb.x; sH[0][hkq + 5][hrow] = hb.y;
        sH[0][hkq + 6][hrow] = hb.z; sH[0][hkq + 7][hrow] = hb.w;
        sW[0][wkq + 0][wn] = wv.x; sW[0][wkq + 1][wn] = wv.y;
        sW[0][wkq + 2][wn] = wv.z; sW[0][wkq + 3][wn] = wv.w;
    }
    __syncthreads();

    int buf = 0;
    // NOTE: outer loop must NOT be unrolled (code-size / compile-time bound).
#pragma unroll 1
    for (int c = 0; c < II / 16; c++) {
        float4 nha, nhb, nwv;
        const bool more = (c + 1 < II / 16);
        if (more) {
            int ko = (c + 1) * 16;
            nha = *(const float4*)(Hptr + ko);
            nhb = *(const float4*)(Hptr + ko + 4);
            nwv = *(const float4*)(Wptr + ko);
        }

#pragma unroll
        for (int kk = 0; kk < 16; kk++) {
            float4 a0 = *(const float4*)&sH[buf][kk][ty * 8];
            float4 a1 = *(const float4*)&sH[buf][kk][ty * 8 + 4];
            float2 bb = *(const float2*)&sW[buf][kk][tx * 2];
            float av[8] = {a0.x, a0.y, a0.z, a0.w, a1.x, a1.y, a1.z, a1.w};
#pragma unroll
            for (int r = 0; r < 8; r++) {
                acc[r][0] += av[r] * bb.x;
                acc[r][1] += av[r] * bb.y;
            }
        }

        if (more) {
            int ob = buf ^ 1;
            sH[ob][hkq + 0][hrow] = nha.x; sH[ob][hkq + 1][hrow] = nha.y;
            sH[ob][hkq + 2][hrow] = nha.z; sH[ob][hkq + 3][hrow] = nha.w;
            sH[ob][hkq + 4][hrow] = nhb.x; sH[ob][hkq + 5][hrow] = nhb.y;
            sH[ob][hkq + 6][hrow] = nhb.z; sH[ob][hkq + 7][hrow] = nhb.w;
            sW[ob][wkq + 0][wn] = nwv.x; sW[ob][wkq + 1][wn] = nwv.y;
            sW[ob][wkq + 2][wn] = nwv.z; sW[ob][wkq + 3][wn] = nwv.w;
            __syncthreads();
            buf = ob;
        }
    }

    // gates tile -> smem (add x-projection and recurrent bias)
#pragma unroll
    for (int r = 0; r < 8; r++) {
#pragma unroll
        for (int cc = 0; cc < 2; cc++) {
            int row = ty * 8 + r;
            int col = tx * 2 + cc;
            int nglob = (col >> 3) * HH + j0 + (col & 7);
            sG[row][col] = acc[r][cc] + xg_t[(size_t)row * NG + nglob] + bhh[nglob];
        }
    }
    __syncthreads();

    // pointwise update: 512 (row, hc) pairs, 4 per thread
#pragma unroll
    for (int u = 0; u < 4; u++) {
        int q = tid * 4 + u;
        int row = q >> 3;
        int hc = q & 7;
        float iv = sigf(sG[row][hc]);
        float fv = sigf(sG[row][8 + hc]);
        float gv = tanhf(sG[row][16 + hc]);
        float ov = sigf(sG[row][24 + hc]);
        int gi = row * HH + j0 + hc;
        float cv = fv * g_c[gi] + iv * gv;
        g_c[gi] = cv;
        Hout[gi] = ov * tanhf(cv);
    }
}

// ---------------------------------------------------------------------------
__global__ void initc_kernel(const float* __restrict__ c0) {
    int i = blockIdx.x * blockDim.x + threadIdx.x;
    if (i < BB * HH) g_c[i] = c0[i];
}

__global__ void finalize_kernel(const float* __restrict__ hlast,
                                float* __restrict__ outh,
                                float* __restrict__ outc) {
    int i = blockIdx.x * blockDim.x + threadIdx.x;
    if (i < BB * HH) {
        outh[i] = hlast[i];
        outc[i] = g_c[i];
    }
}

// ---------------------------------------------------------------------------
extern "C" void kernel_launch(void* const* d_in, const int* in_sizes, int n_in,
                              void* d_out, int out_size) {
    (void)n_in; (void)in_sizes;
    const float* x   = (const float*)d_in[0];  // [T, B, I]
    const float* h0  = (const float*)d_in[1];  // [B, H]
    const float* c0  = (const float*)d_in[2];  // [B, H]
    const float* Wih = (const float*)d_in[3];  // [4H, I]
    const float* Whh = (const float*)d_in[4];  // [4H, H]
    const float* bih = (const float*)d_in[5];
    const float* bhh = (const float*)d_in[6];
    float* out = (float*)d_out;

    // 1) input-side projections for all timesteps
    dim3 g1(NG / 128, (TT * BB) / 128);
    xgemm_kernel<<<g1, 256>>>(x, Wih, bih);

    // 2) cell-state init (inside the graph -> deterministic across replays)
    initc_kernel<<<(BB * HH + 255) / 256, 256>>>(c0);

    // 3) recurrence: outputs buffer doubles as the h ring
    for (int t = 0; t < TT; t++) {
        const float* hprev = (t == 0) ? h0 : out + (size_t)(t - 1) * BB * HH;
        float* hout = out + (size_t)t * BB * HH;
        lstm_step_kernel<<<HH / 8, 128>>>(hprev, Whh, bhh, hout, t);
    }

    // 4) (hT, cT) tail if the output buffer carries them
    long long need = (long long)TT * BB * HH + 2LL * BB * HH;
    if ((long long)out_size >= need) {
        const float* hlast = out + (size_t)(TT - 1) * BB * HH;
        float* outh = out + (size_t)TT * BB * HH;
        float* outc = outh + BB * HH;
        finalize_kernel<<<(BB * HH + 255) / 256, 256>>>(hlast, outh, outc);
    }
}